// round 14
// baseline (speedup 1.0000x reference)
#include <cuda_runtime.h>

#define TPB 256
#define NANN 32
#define NC 80
#define MAXB 16
#define CHUNK_A 64                        // anchors per chunk
#define CHUNK_BYTES (CHUNK_A * NC * 4)    // 20480
#define NCHUNK 4

// dynamic smem layout (bytes)
#define OFF_BUF   0
#define OFF_W     (NCHUNK * CHUNK_BYTES)          // 81920, 256 floats
#define OFF_BOX   (OFF_W + 1024)                  // 82944, 32 float4
#define OFF_AREA  (OFF_BOX + 512)                 // 83456, 32 floats
#define OFF_LBL   (OFF_AREA + 128)                // 83584, 32 floats
#define OFF_RED   (OFF_LBL + 128)                 // 83712, 3*8 floats
#define OFF_MBAR  (OFF_RED + 96)                  // 83808, 4*8 bytes
#define SMEM_TOTAL (OFF_MBAR + 64)                // 83872

__device__ float g_acc[MAXB * 3];        // per image: cls_sum, reg_sum, num_pos
__device__ unsigned int g_count = 0;     // completed-block counter (self-resetting)

__device__ __forceinline__ float fsqrt_approx(float x) {
    float r; asm("sqrt.approx.f32 %0, %1;" : "=f"(r) : "f"(x)); return r;
}
__device__ __forceinline__ float flg2_approx(float x) {
    float r; asm("lg2.approx.f32 %0, %1;" : "=f"(r) : "f"(x)); return r;
}
__device__ __forceinline__ unsigned smem_u32(const void* p) {
    unsigned r;
    asm("{ .reg .u64 t; cvta.to.shared.u64 t, %1; cvt.u32.u64 %0, t; }"
        : "=r"(r) : "l"(p));
    return r;
}
__device__ __forceinline__ void mbar_init(unsigned a, unsigned cnt) {
    asm volatile("mbarrier.init.shared.b64 [%0], %1;" :: "r"(a), "r"(cnt) : "memory");
}
__device__ __forceinline__ void mbar_expect_tx(unsigned a, unsigned bytes) {
    asm volatile("mbarrier.arrive.expect_tx.shared.b64 _, [%0], %1;"
                 :: "r"(a), "r"(bytes) : "memory");
}
__device__ __forceinline__ void bulk_g2s(unsigned dst, const void* src,
                                         unsigned bytes, unsigned mbar) {
    asm volatile(
        "cp.async.bulk.shared::cluster.global.mbarrier::complete_tx::bytes "
        "[%0], [%1], %2, [%3];"
        :: "r"(dst), "l"(src), "r"(bytes), "r"(mbar) : "memory");
}
__device__ __forceinline__ void mbar_wait_p0(unsigned a) {
    unsigned done;
    asm volatile(
        "{\n\t.reg .pred p;\n\t"
        "mbarrier.try_wait.parity.acquire.cta.shared::cta.b64 p, [%1], 0;\n\t"
        "selp.b32 %0, 1, 0, p;\n\t}"
        : "=r"(done) : "r"(a) : "memory");
    if (!done) {
        asm volatile(
            "{\n\t.reg .pred P1;\n\t"
            "W_%=:\n\t"
            "mbarrier.try_wait.parity.acquire.cta.shared::cta.b64 P1, [%0], 0, 0x989680;\n\t"
            "@P1 bra.uni D_%=;\n\t"
            "bra.uni W_%=;\n\t"
            "D_%=:\n\t}"
            :: "r"(a) : "memory");
    }
}

#define LN2F 0.6931471805599453f
#define COEF_NEG (-0.75f * LN2F)    // term = COEF * sqrt(p) * lg2(1-p)
#define COEF_POS (-0.25f * LN2F)

__global__ __launch_bounds__(TPB) void focal_fused_kernel(
    const float* __restrict__ cls,     // [B,K,C]
    const float* __restrict__ regs,    // [B,K,4]
    const float* __restrict__ anc,     // [1,K,4]
    const float* __restrict__ ann,     // [B,NANN,5]
    float* __restrict__ out,
    int K, int B)
{
    extern __shared__ char smem[];
    float*  buf    = (float*) (smem + OFF_BUF);
    float*  s_w    = (float*) (smem + OFF_W);
    float4* s_box  = (float4*)(smem + OFF_BOX);
    float*  s_area = (float*) (smem + OFF_AREA);
    float*  s_lbl  = (float*) (smem + OFF_LBL);
    float*  s_red  = (float*) (smem + OFF_RED);     // [3][8]
    const unsigned mbar0 = smem_u32(smem + OFF_MBAR);

    const int b    = blockIdx.y;
    const int s    = blockIdx.x * TPB;
    const int tid  = threadIdx.x;
    const int wid  = tid >> 5;
    const int lane = tid & 31;
    const int navail = min(TPB, K - s);    // anchors this block actually owns

    if (tid < NANN) {
        const float* a = ann + (size_t)b * NANN * 5 + tid * 5;
        float x1 = a[0], y1 = a[1], x2 = a[2], y2 = a[3];
        s_box[tid]  = make_float4(x1, y1, x2, y2);
        s_area[tid] = (x2 - x1) * (y2 - y1);
        s_lbl[tid]  = a[4];
    }
    if (tid == 0) {
        #pragma unroll
        for (int c = 0; c < NCHUNK; c++) mbar_init(mbar0 + c * 8, 1);
    }
    __syncthreads();

    // ---- kick off all bulk copies immediately (overlap with phase 1) -------
    if (tid == 0) {
        const char* src0 = (const char*)(cls + ((size_t)b * K + s) * NC);
        #pragma unroll
        for (int c = 0; c < NCHUNK; c++) {
            const int na = min(CHUNK_A, navail - c * CHUNK_A);
            if (na > 0) {
                const unsigned bytes = (unsigned)na * NC * 4;
                mbar_expect_tx(mbar0 + c * 8, bytes);
                bulk_g2s(smem_u32(buf) + c * CHUNK_BYTES,
                         src0 + (size_t)c * CHUNK_BYTES, bytes, mbar0 + c * 8);
            }
        }
    }

    // ---------------- phase 1: IoU match (round-11 form, frozen) ------------
    float reg_sum = 0.0f, npos = 0.0f, corr = 0.0f, wgt = 0.0f;
    const int k = s + tid;

    if (k < K) {
        const float4 av = *(const float4*)(anc + 4*(size_t)k);
        const float ax1 = av.x, ay1 = av.y, ax2 = av.z, ay2 = av.w;
        const float area_a = (ax2 - ax1) * (ay2 - ay1);

        float best_in = -1.0f, best_un = 1.0f;
        int   bi = 0;
        #pragma unroll 8
        for (int n = 0; n < NANN; n++) {
            const float4 bb = s_box[n];
            float iw = fmaxf(fminf(ax2, bb.z) - fmaxf(ax1, bb.x), 0.0f);
            float ih = fmaxf(fminf(ay2, bb.w) - fmaxf(ay1, bb.y), 0.0f);
            float inter = iw * ih;
            float uni   = area_a + s_area[n] - inter;
            if (inter * best_un > best_in * uni) {      // strict > == first-argmax
                best_in = inter; best_un = uni; bi = n;
            }
        }

        const bool pos = (best_in >= 0.5f * best_un);
        const bool neg = (best_in <  0.4f * best_un);
        wgt = (pos || neg) ? COEF_NEG : 0.0f;

        if (pos) {
            npos = 1.0f;
            const int state = (int)s_lbl[bi];
            const float4 gb = s_box[bi];
            const float aw  = ax2 - ax1, ah = ay2 - ay1;
            const float acx = ax1 + 0.5f * aw, acy = ay1 + 0.5f * ah;
            const float gw  = fmaxf(gb.z - gb.x, 1.0f);
            const float gh  = fmaxf(gb.w - gb.y, 1.0f);
            const float gcx = gb.x + 0.5f * gw, gcy = gb.y + 0.5f * gh;
            float t0 = (gcx - acx) / aw * 10.0f;
            float t1 = (gcy - acy) / ah * 10.0f;
            float t2 = __logf(gw / aw) * 5.0f;
            float t3 = __logf(gh / ah) * 5.0f;
            const float4 r = *(const float4*)(regs + ((size_t)b * K + k) * 4);
            float d0 = fabsf(t0 - r.x), d1 = fabsf(t1 - r.y);
            float d2 = fabsf(t2 - r.z), d3 = fabsf(t3 - r.w);
            const float th = 1.0f / 9.0f, off = 0.5f / 9.0f;
            reg_sum += (d0 <= th) ? 4.5f * d0 * d0 : d0 - off;
            reg_sum += (d1 <= th) ? 4.5f * d1 * d1 : d1 - off;
            reg_sum += (d2 <= th) ? 4.5f * d2 * d2 : d2 - off;
            reg_sum += (d3 <= th) ? 4.5f * d3 * d3 : d3 - off;

            const float pc = cls[((size_t)b * K + k) * NC + state];
            corr = COEF_POS * fsqrt_approx(1.0f - pc) * flg2_approx(pc)
                 - COEF_NEG * fsqrt_approx(pc) * flg2_approx(1.0f - pc);
        }
    }
    s_w[tid] = wgt;
    __syncthreads();

    // ---------------- phase 2: consume smem chunks ---------------------------
    // chunk c: 64 anchors, 4 lanes per anchor (a = tid>>2, q = tid&3).
    // LDS pattern is conflict-free (32 distinct banks per 8-lane phase).
    float cls_sum = corr;
    const int a_loc = tid >> 2;
    const int qlan  = tid & 3;

    #define TERM(acc, pv)                                                    \
        {                                                                    \
            const float q_ = fmaf((pv), -1.0f, 1.0f);   /* FFMA-imm */       \
            acc = fmaf(fsqrt_approx(pv), flg2_approx(q_), acc);              \
        }

    #pragma unroll
    for (int c = 0; c < NCHUNK; c++) {
        const int na = min(CHUNK_A, navail - c * CHUNK_A);
        if (na <= 0) break;
        mbar_wait_p0(mbar0 + c * 8);
        if (a_loc < na) {
            const float* pb = buf + (size_t)c * CHUNK_A * NC + a_loc * NC + qlan * 4;
            const float w = s_w[c * CHUNK_A + a_loc];
            float b0 = 0.0f, b1 = 0.0f, b2 = 0.0f, b3 = 0.0f;
            #pragma unroll
            for (int j = 0; j < 5; j++) {
                const float4 v = ((const float4*)pb)[j * 4];   // +64B steps
                TERM(b0, v.x);
                TERM(b1, v.y);
                TERM(b2, v.z);
                TERM(b3, v.w);
            }
            cls_sum = fmaf(w, (b0 + b1) + (b2 + b3), cls_sum);
        }
    }
    #undef TERM

    // ---------------- block reduction + finalize ------------------------------
    #pragma unroll
    for (int o = 16; o > 0; o >>= 1) {
        cls_sum += __shfl_down_sync(0xffffffffu, cls_sum, o);
        reg_sum += __shfl_down_sync(0xffffffffu, reg_sum, o);
        npos    += __shfl_down_sync(0xffffffffu, npos, o);
    }
    if (lane == 0) {
        s_red[0 * 8 + wid] = cls_sum;
        s_red[1 * 8 + wid] = reg_sum;
        s_red[2 * 8 + wid] = npos;
    }
    __syncthreads();

    if (tid == 0) {
        float c = 0.0f, r = 0.0f, n = 0.0f;
        #pragma unroll
        for (int i = 0; i < TPB / 32; i++) {
            c += s_red[0 * 8 + i]; r += s_red[1 * 8 + i]; n += s_red[2 * 8 + i];
        }
        atomicAdd(&g_acc[b*3+0], c);
        atomicAdd(&g_acc[b*3+1], r);
        atomicAdd(&g_acc[b*3+2], n);
        __threadfence();

        const unsigned int total = gridDim.x * gridDim.y;
        const unsigned int old = atomicAdd(&g_count, 1u);
        if (old == total - 1u) {
            float cs = 0.0f, rs = 0.0f;
            for (int bb = 0; bb < B; bb++) {
                const float acc_c = atomicAdd(&g_acc[bb*3+0], 0.0f);
                const float acc_r = atomicAdd(&g_acc[bb*3+1], 0.0f);
                const float np    = atomicAdd(&g_acc[bb*3+2], 0.0f);
                cs += acc_c / fmaxf(np, 1.0f);
                rs += (np > 0.0f) ? acc_r / fmaxf(np * 4.0f, 1.0f) : 0.0f;
            }
            out[0] = cs / (float)B;
            out[1] = rs / (float)B;
            for (int i = 0; i < B * 3; i++) g_acc[i] = 0.0f;
            __threadfence();
            g_count = 0u;
            __threadfence();
        }
    }
}

extern "C" void kernel_launch(void* const* d_in, const int* in_sizes, int n_in,
                              void* d_out, int out_size) {
    const float* cls  = (const float*)d_in[0];   // [B,K,C]
    const float* regs = (const float*)d_in[1];   // [B,K,4]
    const float* anc  = (const float*)d_in[2];   // [1,K,4]
    const float* ann  = (const float*)d_in[3];   // [B,NANN,5]

    const int K = in_sizes[2] / 4;
    const int B = in_sizes[3] / (NANN * 5);

    cudaFuncSetAttribute(focal_fused_kernel,
                         cudaFuncAttributeMaxDynamicSharedMemorySize, SMEM_TOTAL);

    dim3 grid((K + TPB - 1) / TPB, B);
    focal_fused_kernel<<<grid, TPB, SMEM_TOTAL>>>(cls, regs, anc, ann,
                                                  (float*)d_out, K, B);
}